// round 1
// baseline (speedup 1.0000x reference)
#include <cuda_runtime.h>
#include <cuda_bf16.h>
#include <cstdint>

// ---------------------------------------------------------------------------
// GMDTW (soft-DTW, gamma=1) for m1=m2=2048, d=128.
// Phase 1: C~[i][j] = (||y_i||^2 + ||x2_j||^2 - 2 y_i.x2_j) * log2(e)   (log2 domain)
// Phase 2: wavefront DP over 4095 anti-diagonals:
//   R[i,j] = C[i-1,j-1] + m - log2(2^(m-a)+2^(m-b)+2^(m-c)),  m=min(a,b,c)
//   a=R[i-1,j], b=R[i,j-1], c=R[i-1,j-1]; borders = +inf, R[0,0]=0.
// Output: R[2048,2048] * ln2.
// ---------------------------------------------------------------------------

#define M1 2048
#define M2 2048
#define DIM 128
#define NCTA 64          // DP CTAs (one warp each), 32 rows per CTA
#define KMAX 4096        // last diagonal (i+j)
#define INV_LN2 1.44269504088896340736f
#define LN2F    0.69314718055994530942f

__device__ float g_C[(size_t)M1 * M2];     // cost matrix, log2-scaled, row-major
__device__ float g_n1[M1];
__device__ float g_n2[M2];
__device__ float g_bnd[NCTA][4112];        // g_bnd[w][k] = R~[k][row (w+1)*32]
__device__ int   g_prog[NCTA];             // last diag published by CTA w

// ---------------------------------------------------------------------------

__device__ __forceinline__ float ex2f(float x) {
    float r; asm("ex2.approx.f32 %0, %1;" : "=f"(r) : "f"(x)); return r;
}
__device__ __forceinline__ float lg2f(float x) {
    float r; asm("lg2.approx.f32 %0, %1;" : "=f"(r) : "f"(x)); return r;
}
__device__ __forceinline__ int acq_load(const int* p) {
    int v; asm volatile("ld.global.acquire.gpu.b32 %0, [%1];" : "=r"(v) : "l"(p) : "memory");
    return v;
}
__device__ __forceinline__ void rel_store(int* p, int v) {
    asm volatile("st.global.release.gpu.b32 [%0], %1;" :: "l"(p), "r"(v) : "memory");
}
__device__ __forceinline__ void waitprog(const int* p, int need, int& known) {
    if (known >= need) return;
    int v;
    do {
        v = acq_load(p);
        if (v < need) __nanosleep(40);
    } while (v < need);
    known = v;
}
__device__ __forceinline__ float pick4(float4 v, int q) {
    float lo = (q & 1) ? v.y : v.x;
    float hi = (q & 1) ? v.w : v.z;
    return (q & 2) ? hi : lo;
}

// ---------------------------------------------------------------------------
// init: reset progress counters (must happen every graph replay)
__global__ void init_k() {
    if (threadIdx.x < NCTA) g_prog[threadIdx.x] = 0;
}

// ---------------------------------------------------------------------------
// squared norms: one warp per row (4096 rows total: y then x2)
__global__ void __launch_bounds__(256) norms_k(const float* __restrict__ y,
                                               const float* __restrict__ x2) {
    int w = blockIdx.x * 8 + (threadIdx.x >> 5);
    int lane = threadIdx.x & 31;
    if (w >= 2 * M1) return;
    const float* src = (w < M1) ? (y + (size_t)w * DIM) : (x2 + (size_t)(w - M1) * DIM);
    float4 v = ((const float4*)src)[lane];
    float s = v.x * v.x + v.y * v.y + v.z * v.z + v.w * v.w;
#pragma unroll
    for (int o = 16; o; o >>= 1) s += __shfl_xor_sync(0xffffffffu, s, o);
    if (lane == 0) {
        if (w < M1) g_n1[w] = s; else g_n2[w - M1] = s;
    }
}

// ---------------------------------------------------------------------------
// GEMM: 64x64 tile, 256 threads, 4x4 microtile, K chunks of 32.
// C~[i][j] = (n1[i] + n2[j] - 2*dot) * INV_LN2
__global__ void __launch_bounds__(256) gemm_k(const float* __restrict__ A,
                                              const float* __restrict__ B) {
    __shared__ float As[32][68];
    __shared__ float Bs[32][68];
    const int t  = threadIdx.x;
    const int tx = t & 15, ty = t >> 4;
    const int bi = blockIdx.y << 6, bj = blockIdx.x << 6;
    const int lrow = t >> 2;
    const int lk   = (t & 3) << 3;

    float acc[4][4];
#pragma unroll
    for (int u = 0; u < 4; ++u)
#pragma unroll
        for (int v = 0; v < 4; ++v) acc[u][v] = 0.0f;

    const float* Ap = A + (size_t)(bi + lrow) * DIM + lk;
    const float* Bp = B + (size_t)(bj + lrow) * DIM + lk;

    for (int k0 = 0; k0 < DIM; k0 += 32) {
        float4 a0 = *(const float4*)(Ap + k0);
        float4 a1 = *(const float4*)(Ap + k0 + 4);
        float4 b0 = *(const float4*)(Bp + k0);
        float4 b1 = *(const float4*)(Bp + k0 + 4);
        __syncthreads();
        As[lk + 0][lrow] = a0.x; As[lk + 1][lrow] = a0.y;
        As[lk + 2][lrow] = a0.z; As[lk + 3][lrow] = a0.w;
        As[lk + 4][lrow] = a1.x; As[lk + 5][lrow] = a1.y;
        As[lk + 6][lrow] = a1.z; As[lk + 7][lrow] = a1.w;
        Bs[lk + 0][lrow] = b0.x; Bs[lk + 1][lrow] = b0.y;
        Bs[lk + 2][lrow] = b0.z; Bs[lk + 3][lrow] = b0.w;
        Bs[lk + 4][lrow] = b1.x; Bs[lk + 5][lrow] = b1.y;
        Bs[lk + 6][lrow] = b1.z; Bs[lk + 7][lrow] = b1.w;
        __syncthreads();
#pragma unroll
        for (int kk = 0; kk < 32; ++kk) {
            float4 av = *(const float4*)&As[kk][ty << 2];
            float4 bv = *(const float4*)&Bs[kk][tx << 2];
            float a_[4] = {av.x, av.y, av.z, av.w};
            float b_[4] = {bv.x, bv.y, bv.z, bv.w};
#pragma unroll
            for (int u = 0; u < 4; ++u)
#pragma unroll
                for (int v = 0; v < 4; ++v) acc[u][v] += a_[u] * b_[v];
        }
    }

    float4 nb = *(const float4*)&g_n2[bj + (tx << 2)];
#pragma unroll
    for (int u = 0; u < 4; ++u) {
        int i = bi + (ty << 2) + u;
        float na = g_n1[i];
        float4 o;
        o.x = (na + nb.x - 2.0f * acc[u][0]) * INV_LN2;
        o.y = (na + nb.y - 2.0f * acc[u][1]) * INV_LN2;
        o.z = (na + nb.z - 2.0f * acc[u][2]) * INV_LN2;
        o.w = (na + nb.w - 2.0f * acc[u][3]) * INV_LN2;
        *(float4*)&g_C[(size_t)i * M2 + bj + (tx << 2)] = o;
    }
}

// ---------------------------------------------------------------------------
// DP wavefront: 64 single-warp CTAs, row-stationary, shuffle neighbors,
// cross-CTA pipeline via release/acquire progress + float4-prefetched boundary.
__global__ void __launch_bounds__(32, 1) dp_k(float* __restrict__ out) {
    const int cta  = blockIdx.x;
    const int lane = threadIdx.x;
    const int i    = cta * 32 + lane + 1;     // 1-based row
    const int r    = i - 1;                   // 0-based row
    const float* crow = g_C + (size_t)r * M2;
    const int ip   = cta * 32;                // 1-based row above this CTA's block
    const int k0   = ip + 2;
    const int k1   = ip + 32 + M2;            // <= 4096 always
    const int wend = ip + M2;                 // last diag with a valid boundary value

    const float INFV = __int_as_float(0x7f800000);

    float r1 = INFV, r2 = INFV;               // own row @ diag k-1, k-2
    float bk1 = INFV, bk2 = INFV;             // boundary row ip @ diag k-1, k-2

    // lane-0 boundary pipeline state
    float4 bb = make_float4(0, 0, 0, 0), bbn = make_float4(0, 0, 0, 0);
    int tb = 0, known = 0;
    const int*   prog_p = (cta > 0) ? &g_prog[cta - 1] : &g_prog[0];
    const float* brow   = (cta > 0) ? g_bnd[cta - 1]   : g_bnd[0];

    if (lane == 0) {
        if (cta == 0) {
            bk1 = INFV;
            bk2 = 0.0f;                        // R[0][0] = 0 (used at k=2)
        } else {
            int tfirst = ip + 1;
            tb = tfirst & ~3;
            int tgt0 = tb + 3 < wend ? tb + 3 : wend;
            waitprog(prog_p, tgt0, known);
            bb = __ldcg((const float4*)(brow + tb));
            int tgt1 = tb + 7 < wend ? tb + 7 : wend;
            waitprog(prog_p, tgt1, known);
            bbn = __ldcg((const float4*)(brow + tb + 4));
            bk1 = pick4(bb, tfirst & 3);
            bk2 = INFV;
        }
    }

    // C-row prefetch pipeline
    float4 cnext = *(const float4*)crow;       // block for c in [0,3]
    float4 cbuf  = cnext;

    for (int k = k0; k <= k1; ++k) {
        const int c = k - i - 1;               // 0-based column
        const bool valid = (c >= 0) & (c < M2);

        float cost = 0.0f;
        if (valid) {
            if ((c & 3) == 0) {
                cbuf = cnext;
                int cn = c + 4; if (cn > M2 - 4) cn = M2 - 4;
                cnext = *(const float4*)(crow + cn);
            }
            cost = pick4(cbuf, c & 3);
        }

        float up = __shfl_up_sync(0xffffffffu, r1, 1);
        float dg = __shfl_up_sync(0xffffffffu, r2, 1);
        if (lane == 0) { up = bk1; dg = bk2; }

        float rnew = INFV;
        if (valid) {
            float m = fminf(fminf(up, r1), dg);
            float s = ex2f(m - up) + ex2f(m - r1) + ex2f(m - dg);
            rnew = cost + (m - lg2f(s));
        }

        if (lane == 31 && cta < NCTA - 1) {
            g_bnd[cta][k] = rnew;              // data
            rel_store(&g_prog[cta], k);        // publish
        }

        if (lane == 0) {                       // advance boundary for next iter
            bk2 = bk1;
            if (cta == 0) {
                bk1 = INFV;
            } else {
                int t = k;                     // next iteration needs B[k]
                if (t > wend) {
                    bk1 = INFV;
                } else {
                    if (t >= tb + 4) {
                        tb += 4;
                        bb = bbn;
                        int tgt = tb + 7 < wend ? tb + 7 : wend;
                        waitprog(prog_p, tgt, known);
                        bbn = __ldcg((const float4*)(brow + tb + 4));
                    }
                    bk1 = pick4(bb, t & 3);
                }
            }
        }

        r2 = r1; r1 = rnew;
    }

    if (cta == NCTA - 1 && lane == 31) {
        out[0] = r1 * LN2F;                    // back to nat-log domain
    }
}

// ---------------------------------------------------------------------------
extern "C" void kernel_launch(void* const* d_in, const int* in_sizes, int n_in,
                              void* d_out, int out_size) {
    const float* y  = (const float*)d_in[0];
    const float* x2 = (const float*)d_in[1];
    float* out = (float*)d_out;

    init_k<<<1, 64>>>();
    norms_k<<<512, 256>>>(y, x2);
    gemm_k<<<dim3(M2 / 64, M1 / 64), 256>>>(y, x2);
    dp_k<<<NCTA, 32>>>(out);
}

// round 2
// speedup vs baseline: 2.6440x; 2.6440x over previous
#include <cuda_runtime.h>
#include <cuda_bf16.h>
#include <cstdint>

// ---------------------------------------------------------------------------
// GMDTW (soft-DTW, gamma=1) for m1=m2=2048, d=128.
// Phase 1: C~[i][j] = (||y_i||^2 + ||x2_j||^2 - 2 y_i.x2_j) * log2(e)
// Phase 2: wavefront DP, 32 single-warp CTAs x 64 rows, 2 cells/lane,
//          cross-CTA boundary pipelined through L2 (release/acquire, per-4).
// ---------------------------------------------------------------------------

#define M1 2048
#define M2 2048
#define DIM 128
#define NCTA 32
#define ROWS 64
#define INV_LN2 1.44269504088896340736f
#define LN2F    0.69314718055994530942f

__device__ float g_C[(size_t)M1 * M2];
__device__ float g_n1[M1];
__device__ float g_n2[M2];
__device__ float g_bnd[NCTA][4112];
__device__ int   g_prog[NCTA];

__device__ __forceinline__ float ex2f(float x) {
    float r; asm("ex2.approx.f32 %0, %1;" : "=f"(r) : "f"(x)); return r;
}
__device__ __forceinline__ float lg2f(float x) {
    float r; asm("lg2.approx.f32 %0, %1;" : "=f"(r) : "f"(x)); return r;
}
__device__ __forceinline__ int acq_load(const int* p) {
    int v; asm volatile("ld.global.acquire.gpu.b32 %0, [%1];" : "=r"(v) : "l"(p) : "memory");
    return v;
}
__device__ __forceinline__ void rel_store(int* p, int v) {
    asm volatile("st.global.release.gpu.b32 [%0], %1;" :: "l"(p), "r"(v) : "memory");
}
__device__ __forceinline__ void waitprog(const int* p, int need, int& known) {
    if (known >= need) return;
    int v;
    do { v = acq_load(p); } while (v < need);
    known = v;
}
__device__ __forceinline__ float pick4(float4 v, int q) {
    float lo = (q & 1) ? v.y : v.x;
    float hi = (q & 1) ? v.w : v.z;
    return (q & 2) ? hi : lo;
}
__device__ __forceinline__ float cellf(float cost, float up, float lf, float dg) {
    float m = fminf(fminf(up, lf), dg);
    float s = ex2f(m - up) + ex2f(m - lf) + ex2f(m - dg);
    return cost + (m - lg2f(s));
}

// ---------------------------------------------------------------------------
__global__ void init_k() {
    if (threadIdx.x < NCTA) g_prog[threadIdx.x] = 0;
}

__global__ void __launch_bounds__(256) norms_k(const float* __restrict__ y,
                                               const float* __restrict__ x2) {
    int w = blockIdx.x * 8 + (threadIdx.x >> 5);
    int lane = threadIdx.x & 31;
    if (w >= 2 * M1) return;
    const float* src = (w < M1) ? (y + (size_t)w * DIM) : (x2 + (size_t)(w - M1) * DIM);
    float4 v = ((const float4*)src)[lane];
    float s = v.x * v.x + v.y * v.y + v.z * v.z + v.w * v.w;
#pragma unroll
    for (int o = 16; o; o >>= 1) s += __shfl_xor_sync(0xffffffffu, s, o);
    if (lane == 0) {
        if (w < M1) g_n1[w] = s; else g_n2[w - M1] = s;
    }
}

__global__ void __launch_bounds__(256) gemm_k(const float* __restrict__ A,
                                              const float* __restrict__ B) {
    __shared__ float As[32][68];
    __shared__ float Bs[32][68];
    const int t  = threadIdx.x;
    const int tx = t & 15, ty = t >> 4;
    const int bi = blockIdx.y << 6, bj = blockIdx.x << 6;
    const int lrow = t >> 2;
    const int lk   = (t & 3) << 3;

    float acc[4][4];
#pragma unroll
    for (int u = 0; u < 4; ++u)
#pragma unroll
        for (int v = 0; v < 4; ++v) acc[u][v] = 0.0f;

    const float* Ap = A + (size_t)(bi + lrow) * DIM + lk;
    const float* Bp = B + (size_t)(bj + lrow) * DIM + lk;

    for (int k0 = 0; k0 < DIM; k0 += 32) {
        float4 a0 = *(const float4*)(Ap + k0);
        float4 a1 = *(const float4*)(Ap + k0 + 4);
        float4 b0 = *(const float4*)(Bp + k0);
        float4 b1 = *(const float4*)(Bp + k0 + 4);
        __syncthreads();
        As[lk + 0][lrow] = a0.x; As[lk + 1][lrow] = a0.y;
        As[lk + 2][lrow] = a0.z; As[lk + 3][lrow] = a0.w;
        As[lk + 4][lrow] = a1.x; As[lk + 5][lrow] = a1.y;
        As[lk + 6][lrow] = a1.z; As[lk + 7][lrow] = a1.w;
        Bs[lk + 0][lrow] = b0.x; Bs[lk + 1][lrow] = b0.y;
        Bs[lk + 2][lrow] = b0.z; Bs[lk + 3][lrow] = b0.w;
        Bs[lk + 4][lrow] = b1.x; Bs[lk + 5][lrow] = b1.y;
        Bs[lk + 6][lrow] = b1.z; Bs[lk + 7][lrow] = b1.w;
        __syncthreads();
#pragma unroll
        for (int kk = 0; kk < 32; ++kk) {
            float4 av = *(const float4*)&As[kk][ty << 2];
            float4 bv = *(const float4*)&Bs[kk][tx << 2];
            float a_[4] = {av.x, av.y, av.z, av.w};
            float b_[4] = {bv.x, bv.y, bv.z, bv.w};
#pragma unroll
            for (int u = 0; u < 4; ++u)
#pragma unroll
                for (int v = 0; v < 4; ++v) acc[u][v] += a_[u] * b_[v];
        }
    }

    float4 nb = *(const float4*)&g_n2[bj + (tx << 2)];
#pragma unroll
    for (int u = 0; u < 4; ++u) {
        int i = bi + (ty << 2) + u;
        float na = g_n1[i];
        float4 o;
        o.x = (na + nb.x - 2.0f * acc[u][0]) * INV_LN2;
        o.y = (na + nb.y - 2.0f * acc[u][1]) * INV_LN2;
        o.z = (na + nb.z - 2.0f * acc[u][2]) * INV_LN2;
        o.w = (na + nb.w - 2.0f * acc[u][3]) * INV_LN2;
        *(float4*)&g_C[(size_t)i * M2 + bj + (tx << 2)] = o;
    }
}

// ---------------------------------------------------------------------------
// DP wavefront
__global__ void __launch_bounds__(32, 1) dp_k(float* __restrict__ out) {
    const int cta  = blockIdx.x;
    const int lane = threadIdx.x;
    const int base = cta * ROWS;               // boundary row (1-based) above block
    const int iA   = base + lane + 1;          // first owned row (1-based)
    const int iB   = base + 32 + lane + 1;     // second owned row
    const float* crowA = g_C + (size_t)(iA - 1) * M2;
    const float* crowB = g_C + (size_t)(iB - 1) * M2;

    const int k0 = base + 2;
    const int k1 = base + 2115;                // base+2112 real + 3 dummy (k1 % 4 == 3)
    const int wend = (cta > 0) ? (base + 2048) : -1;  // last valid boundary index

    const float INFV = __int_as_float(0x7f800000);

    float rA1 = INFV, rA2 = INFV, rB1 = INFV, rB2 = INFV;
    float q0 = INFV, q1 = INFV, q2 = INFV, q3 = INFV;   // publish shift reg (lane31)
    float res = INFV;

    // boundary state — tracked uniformly by ALL lanes (only lane 0 consumes)
    float bk1, bk2;
    float4 bb = make_float4(0, 0, 0, 0), bbn = make_float4(0, 0, 0, 0);
    int tb = 0, known = 0;
    const int*   prog_p = &g_prog[(cta > 0) ? (cta - 1) : 0];
    const float* brow   = g_bnd[(cta > 0) ? (cta - 1) : 0];

    if (cta == 0) {
        bk1 = INFV; bk2 = 0.0f;                // R[0][0] = 0 feeds cell (1,1) at k=2
    } else {
        tb = base;                             // (base+1) & ~3 == base (base % 4 == 0)
        int tgt = tb + 7 < wend ? tb + 7 : wend;
        waitprog(prog_p, tgt, known);
        bb  = __ldcg((const float4*)(brow + tb));
        bbn = __ldcg((const float4*)(brow + tb + 4));
        bk1 = bb.y;                            // B[base+1]
        bk2 = INFV;                            // B[base] = border
    }

    // cost pipelines, depth 3
    float ca0, ca1, ca2, cb0, cb1, cb2;
    {
        int c;
        c = k0 + 0 - iA - 1; c = min(max(c, 0), M2 - 1); ca0 = __ldg(crowA + c);
        c = k0 + 1 - iA - 1; c = min(max(c, 0), M2 - 1); ca1 = __ldg(crowA + c);
        c = k0 + 2 - iA - 1; c = min(max(c, 0), M2 - 1); ca2 = __ldg(crowA + c);
        c = k0 + 0 - iB - 1; c = min(max(c, 0), M2 - 1); cb0 = __ldg(crowB + c);
        c = k0 + 1 - iB - 1; c = min(max(c, 0), M2 - 1); cb1 = __ldg(crowB + c);
        c = k0 + 2 - iB - 1; c = min(max(c, 0), M2 - 1); cb2 = __ldg(crowB + c);
    }

    for (int k = k0; k <= k1; ++k) {
        // neighbor exchange (pre-update values)
        float upA = __shfl_up_sync(0xffffffffu, rA1, 1);
        float dgA = __shfl_up_sync(0xffffffffu, rA2, 1);
        float upB = __shfl_up_sync(0xffffffffu, rB1, 1);
        float dgB = __shfl_up_sync(0xffffffffu, rB2, 1);
        float tA1 = __shfl_sync(0xffffffffu, rA1, 31);
        float tA2 = __shfl_sync(0xffffffffu, rA2, 31);
        if (lane == 0) { upA = bk1; dgA = bk2; upB = tA1; dgB = tA2; }

        float nA = cellf(ca0, upA, rA1, dgA);
        float nB = cellf(cb0, upB, rB1, dgB);

        bool vA = (k > iA) && (k <= iA + M2);
        bool vB = (k > iB) && (k <= iB + M2);
        rA2 = rA1; rA1 = vA ? nA : INFV;
        rB2 = rB1; rB1 = vB ? nB : INFV;

        if (k == 4096) res = rB1;              // R[2048][2048] (cta 31, lane 31)

        // publish shift register + per-4 publication (uniform outer condition)
        q0 = q1; q1 = q2; q2 = q3; q3 = rB1;
        if ((k & 3) == 3) {
            if (lane == 31) {
                *(float4*)&g_bnd[cta][k - 3] = make_float4(q0, q1, q2, q3);
                rel_store(&g_prog[cta], k);
            }
        }

        // boundary advance for next iteration (uniform across warp)
        bk2 = bk1;
        {
            int t = k;                         // next iter needs B[k]
            if (t > wend) {
                bk1 = INFV;
            } else {
                if (t == tb + 4) {
                    tb += 4;
                    bb = bbn;
                    int tgt = tb + 7 < wend ? tb + 7 : wend;
                    waitprog(prog_p, tgt, known);
                    bbn = __ldcg((const float4*)(brow + tb + 4));
                }
                bk1 = pick4(bb, t & 3);
            }
        }

        // cost pipeline advance
        ca0 = ca1; ca1 = ca2;
        cb0 = cb1; cb1 = cb2;
        int cA = k + 3 - iA - 1; cA = min(max(cA, 0), M2 - 1);
        int cB = k + 3 - iB - 1; cB = min(max(cB, 0), M2 - 1);
        ca2 = __ldg(crowA + cA);
        cb2 = __ldg(crowB + cB);
    }

    if (cta == NCTA - 1 && lane == 31) {
        out[0] = res * LN2F;
    }
}

// ---------------------------------------------------------------------------
extern "C" void kernel_launch(void* const* d_in, const int* in_sizes, int n_in,
                              void* d_out, int out_size) {
    const float* y  = (const float*)d_in[0];
    const float* x2 = (const float*)d_in[1];
    float* out = (float*)d_out;

    init_k<<<1, 32>>>();
    norms_k<<<512, 256>>>(y, x2);
    gemm_k<<<dim3(M2 / 64, M1 / 64), 256>>>(y, x2);
    dp_k<<<NCTA, 32>>>(out);
}

// round 3
// speedup vs baseline: 5.9763x; 2.2603x over previous
#include <cuda_runtime.h>
#include <cuda_bf16.h>
#include <cstdint>

// ---------------------------------------------------------------------------
// GMDTW (soft-DTW, gamma=1), m1=m2=2048, d=128. log2-domain DP.
// ---------------------------------------------------------------------------

#define M1 2048
#define M2 2048
#define DIM 128
#define NCTA 32
#define CSTR 2176            // padded row stride of cost matrix
#define CPAD 32              // front pad
#define INV_LN2 1.44269504088896340736f
#define LN2F    0.69314718055994530942f

__device__ float g_C[(size_t)M1 * CSTR];
__device__ float g_n1[M1];
__device__ float g_n2[M2];
__device__ float g_bnd[NCTA][4160];
__device__ int   g_prog[NCTA];

__device__ __forceinline__ float ex2f(float x) {
    float r; asm("ex2.approx.f32 %0, %1;" : "=f"(r) : "f"(x)); return r;
}
__device__ __forceinline__ float lg2f(float x) {
    float r; asm("lg2.approx.f32 %0, %1;" : "=f"(r) : "f"(x)); return r;
}
__device__ __forceinline__ int acq_load(const int* p) {
    int v; asm volatile("ld.global.acquire.gpu.b32 %0, [%1];" : "=r"(v) : "l"(p) : "memory");
    return v;
}
__device__ __forceinline__ void rel_store(int* p, int v) {
    asm volatile("st.global.release.gpu.b32 [%0], %1;" :: "l"(p), "r"(v) : "memory");
}
__device__ __forceinline__ void waitprog(const int* p, int need, int& known) {
    if (known >= need) return;
    int v;
    do { v = acq_load(p); } while (v < need);
    known = v;
}

// ---------------------------------------------------------------------------
__global__ void init_k() {
    if (threadIdx.x < NCTA) g_prog[threadIdx.x] = 0;
}

__global__ void __launch_bounds__(256) norms_k(const float* __restrict__ y,
                                               const float* __restrict__ x2) {
    int w = blockIdx.x * 8 + (threadIdx.x >> 5);
    int lane = threadIdx.x & 31;
    if (w >= 2 * M1) return;
    const float* src = (w < M1) ? (y + (size_t)w * DIM) : (x2 + (size_t)(w - M1) * DIM);
    float4 v = ((const float4*)src)[lane];
    float s = v.x * v.x + v.y * v.y + v.z * v.z + v.w * v.w;
#pragma unroll
    for (int o = 16; o; o >>= 1) s += __shfl_xor_sync(0xffffffffu, s, o);
    if (lane == 0) {
        if (w < M1) g_n1[w] = s; else g_n2[w - M1] = s;
    }
}

__global__ void __launch_bounds__(256) gemm_k(const float* __restrict__ A,
                                              const float* __restrict__ B) {
    __shared__ float As[32][68];
    __shared__ float Bs[32][68];
    const int t  = threadIdx.x;
    const int tx = t & 15, ty = t >> 4;
    const int bi = blockIdx.y << 6, bj = blockIdx.x << 6;
    const int lrow = t >> 2;
    const int lk   = (t & 3) << 3;

    float acc[4][4];
#pragma unroll
    for (int u = 0; u < 4; ++u)
#pragma unroll
        for (int v = 0; v < 4; ++v) acc[u][v] = 0.0f;

    const float* Ap = A + (size_t)(bi + lrow) * DIM + lk;
    const float* Bp = B + (size_t)(bj + lrow) * DIM + lk;

    for (int k0 = 0; k0 < DIM; k0 += 32) {
        float4 a0 = *(const float4*)(Ap + k0);
        float4 a1 = *(const float4*)(Ap + k0 + 4);
        float4 b0 = *(const float4*)(Bp + k0);
        float4 b1 = *(const float4*)(Bp + k0 + 4);
        __syncthreads();
        As[lk + 0][lrow] = a0.x; As[lk + 1][lrow] = a0.y;
        As[lk + 2][lrow] = a0.z; As[lk + 3][lrow] = a0.w;
        As[lk + 4][lrow] = a1.x; As[lk + 5][lrow] = a1.y;
        As[lk + 6][lrow] = a1.z; As[lk + 7][lrow] = a1.w;
        Bs[lk + 0][lrow] = b0.x; Bs[lk + 1][lrow] = b0.y;
        Bs[lk + 2][lrow] = b0.z; Bs[lk + 3][lrow] = b0.w;
        Bs[lk + 4][lrow] = b1.x; Bs[lk + 5][lrow] = b1.y;
        Bs[lk + 6][lrow] = b1.z; Bs[lk + 7][lrow] = b1.w;
        __syncthreads();
#pragma unroll
        for (int kk = 0; kk < 32; ++kk) {
            float4 av = *(const float4*)&As[kk][ty << 2];
            float4 bv = *(const float4*)&Bs[kk][tx << 2];
            float a_[4] = {av.x, av.y, av.z, av.w};
            float b_[4] = {bv.x, bv.y, bv.z, bv.w};
#pragma unroll
            for (int u = 0; u < 4; ++u)
#pragma unroll
                for (int v = 0; v < 4; ++v) acc[u][v] += a_[u] * b_[v];
        }
    }

    float4 nb = *(const float4*)&g_n2[bj + (tx << 2)];
#pragma unroll
    for (int u = 0; u < 4; ++u) {
        int i = bi + (ty << 2) + u;
        float na = g_n1[i];
        float4 o;
        o.x = (na + nb.x - 2.0f * acc[u][0]) * INV_LN2;
        o.y = (na + nb.y - 2.0f * acc[u][1]) * INV_LN2;
        o.z = (na + nb.z - 2.0f * acc[u][2]) * INV_LN2;
        o.w = (na + nb.w - 2.0f * acc[u][3]) * INV_LN2;
        *(float4*)&g_C[(size_t)i * CSTR + CPAD + bj + (tx << 2)] = o;
    }
}

// ---------------------------------------------------------------------------
// DP wavefront: 32 single-warp CTAs x 64 rows (2 rows/lane), unrolled x4.
__global__ void __launch_bounds__(32, 1) dp_k(float* __restrict__ out) {
    const int cta  = blockIdx.x;
    const int lane = threadIdx.x;
    const int base = cta * 64;
    const int iA   = base + lane + 1;
    const int iB   = iA + 32;
    const float* pA = &g_C[(size_t)(iA - 1) * CSTR + CPAD] - (iA + 1);  // pA[k] = C~[iA-1][k-iA-1]
    const float* pB = &g_C[(size_t)(iB - 1) * CSTR + CPAD] - (iB + 1);

    const float INFV = __int_as_float(0x7f800000);

    const int  wend   = (cta > 0) ? (base + 2048) : 0;
    const int* prog_p = &g_prog[(cta > 0) ? (cta - 1) : 0];
    const float* brow = g_bnd[(cta > 0) ? (cta - 1) : 0];
    int known = 0;

    // ---- boundary chunk init: bb = B[base..base+3], bbn = B[base+4..base+7]
    float4 bb, bbn;
    {
        int tgt0 = base + 7 < wend ? base + 7 : wend;
        waitprog(prog_p, tgt0, known);
        if (cta > 0) {
            bb  = __ldcg((const float4*)(brow + base));
            bbn = __ldcg((const float4*)(brow + base + 4));
        } else {
            bb  = make_float4(0.0f, INFV, INFV, INFV);   // B[0]=R[0][0]=0
            bbn = make_float4(INFV, INFV, INFV, INFV);
        }
    }

    float rA1 = INFV, rB1 = INFV;
    float uA  = INFV, uB = INFV;    // previous iteration's (post-override) up values
    if (cta == 0 && lane == 0) uA = 0.0f;  // virtual B[base] = 0 feeds dg at k=base+2
    float p2 = INFV, p3 = INFV;     // publish carry (lane31 rB1 of prev group's pos2/3)
    float res = INFV;

    int g = base + 2;               // group start diagonal (g % 4 == 2)

    // ---- cost prefetch: cur = group g, nxt = group g+4
    float cA0[4], cB0[4], cA1[4], cB1[4];
#pragma unroll
    for (int p = 0; p < 4; ++p) {
        cA0[p] = __ldg(pA + g + p);     cB0[p] = __ldg(pB + g + p);
        cA1[p] = __ldg(pA + g + 4 + p); cB1[p] = __ldg(pB + g + 4 + p);
    }

#pragma unroll 1
    for (int gi = 0; gi < 529; ++gi, g += 4) {
        // prefetch boundary chunk for next group + costs for group g+8
        {
            int tgt = g + 9 < wend ? g + 9 : wend;
            waitprog(prog_p, tgt, known);
        }
        float4 bb2 = __ldcg((const float4*)(brow + g + 6));
        float nA2[4], nB2[4];
#pragma unroll
        for (int p = 0; p < 4; ++p) {
            nA2[p] = __ldg(pA + g + 8 + p);
            nB2[p] = __ldg(pB + g + 8 + p);
        }

        const int d = wend - g;     // guard: boundary idx g+e valid iff e <= d
        float q0, q1;               // lane31 rB1 at pos0/pos1 (for publish)

#pragma unroll
        for (int p = 0; p < 4; ++p) {
            const int k = g + p;
            // boundary components for this position (up idx = k-1, guarded)
            float bcomp = (p == 0) ? bb.y : (p == 1) ? bb.z : (p == 2) ? bb.w : bbn.x;
            float bu = (p - 1 <= d) ? bcomp : INFV;

            float sA = __shfl_up_sync(0xffffffffu, rA1, 1);
            float sB = __shfl_up_sync(0xffffffffu, rB1, 1);
            float tA = __shfl_sync(0xffffffffu, rA1, 31);

            float upA = (lane == 0) ? bu : sA;
            float upB = (lane == 0) ? tA : sB;
            float dgA = uA, dgB = uB;

            float costA = (p < 2) ? ((p == 0) ? cA0[0] : cA0[1]) : ((p == 2) ? cA0[2] : cA0[3]);
            float costB = (p < 2) ? ((p == 0) ? cB0[0] : cB0[1]) : ((p == 2) ? cB0[2] : cB0[3]);

            float mA = fminf(fminf(rA1, dgA), upA);
            float mB = fminf(fminf(rB1, dgB), upB);
            float eA = ex2f(mA - upA) + ex2f(mA - rA1) + ex2f(mA - dgA);
            float eB = ex2f(mB - upB) + ex2f(mB - rB1) + ex2f(mB - dgB);
            float vAv = (costA + mA) - lg2f(eA);
            float vBv = (costB + mB) - lg2f(eB);

            bool vA = (k > iA) & (k <= iA + M2);
            bool vB = (k > iB) & (k <= iB + M2);

            uA = upA; uB = upB;
            rA1 = vA ? vAv : INFV;
            rB1 = vB ? vBv : INFV;

            res = (k == 4096) ? rB1 : res;

            if (p == 0) q0 = rB1;
            if (p == 1) {
                q1 = rB1;
                if (lane == 31) {
                    *(float4*)&g_bnd[cta][g - 2] = make_float4(p2, p3, q0, q1);
                    rel_store(&g_prog[cta], g + 1);
                }
            }
            if (p == 2) p2 = rB1;
            if (p == 3) p3 = rB1;
        }

        // rotate buffers
        bb = bbn; bbn = bb2;
#pragma unroll
        for (int p = 0; p < 4; ++p) {
            cA0[p] = cA1[p]; cB0[p] = cB1[p];
            cA1[p] = nA2[p]; cB1[p] = nB2[p];
        }
    }

    if (cta == NCTA - 1 && lane == 31) {
        out[0] = res * LN2F;
    }
}

// ---------------------------------------------------------------------------
extern "C" void kernel_launch(void* const* d_in, const int* in_sizes, int n_in,
                              void* d_out, int out_size) {
    const float* y  = (const float*)d_in[0];
    const float* x2 = (const float*)d_in[1];
    float* out = (float*)d_out;

    init_k<<<1, 32>>>();
    norms_k<<<512, 256>>>(y, x2);
    gemm_k<<<dim3(M2 / 64, M1 / 64), 256>>>(y, x2);
    dp_k<<<NCTA, 32>>>(out);
}